// round 1
// baseline (speedup 1.0000x reference)
#include <cuda_runtime.h>
#include <math.h>

#define T_  4096
#define D_  768
#define H_  12
#define HD_ 64
#define FF_ 3072

// ---------------- scratch (device globals; no allocation allowed) ------------
__device__ float g_h  [T_ * D_];   // layernorm output (reused for LN1 and LN2)
__device__ float g_q  [T_ * D_];   // head-major [H][T][HD]
__device__ float g_k  [T_ * D_];
__device__ float g_v  [T_ * D_];
__device__ float g_ctx[T_ * D_];   // attention output, [T, D]
__device__ float g_x2 [T_ * D_];   // residual stream after MHA
__device__ float g_ff [T_ * FF_];  // SwiGLU hidden

// ---------------- LayerNorm: one block per row ------------------------------
__global__ void ln_kernel(const float* __restrict__ x, const float* __restrict__ g,
                          const float* __restrict__ s, float* __restrict__ out) {
    int row = blockIdx.x;
    const float* xr = x + row * D_;
    float sum = 0.f, sq = 0.f;
    for (int i = threadIdx.x; i < D_; i += 256) {
        float v = xr[i]; sum += v; sq += v * v;
    }
    __shared__ float ssum[8], ssq[8];
    #pragma unroll
    for (int o = 16; o > 0; o >>= 1) {
        sum += __shfl_down_sync(0xffffffffu, sum, o);
        sq  += __shfl_down_sync(0xffffffffu, sq,  o);
    }
    int w = threadIdx.x >> 5, l = threadIdx.x & 31;
    if (l == 0) { ssum[w] = sum; ssq[w] = sq; }
    __syncthreads();
    if (threadIdx.x == 0) {
        float a = 0.f, b = 0.f;
        #pragma unroll
        for (int i = 0; i < 8; i++) { a += ssum[i]; b += ssq[i]; }
        ssum[0] = a; ssq[0] = b;
    }
    __syncthreads();
    float mean = ssum[0] * (1.f / D_);
    float var  = ssq[0]  * (1.f / D_) - mean * mean;
    float rstd = rsqrtf(var + 1e-5f);
    for (int i = threadIdx.x; i < D_; i += 256)
        out[row * D_ + i] = g[i] * (xr[i] - mean) * rstd + s[i];
}

// ---------------- fused QKV GEMM (writes head-major) -------------------------
// grid: (D_/64, T_/64, 3), block: 16x16. C tile 64x64, BK=16, 4x4 microtile.
__global__ void qkv_kernel(const float* __restrict__ Ah,
                           const float* __restrict__ Wq, const float* __restrict__ Wk,
                           const float* __restrict__ Wv,
                           float* __restrict__ qo, float* __restrict__ ko,
                           float* __restrict__ vo) {
    const float* Bw = (blockIdx.z == 0) ? Wq : (blockIdx.z == 1) ? Wk : Wv;
    float* out      = (blockIdx.z == 0) ? qo : (blockIdx.z == 1) ? ko : vo;
    __shared__ float As[16][68];  // A transposed: As[k][m], padded for f4 + banks
    __shared__ float Bs[16][64];
    float acc[4][4] = {};
    int tx = threadIdx.x, ty = threadIdx.y, tid = ty * 16 + tx;
    int m0 = blockIdx.y * 64, n0 = blockIdx.x * 64;
    for (int k0 = 0; k0 < D_; k0 += 16) {
        #pragma unroll
        for (int e = 0; e < 4; e++) {
            int idx = tid + e * 256; int r = idx >> 4, c = idx & 15;
            As[c][r] = Ah[(m0 + r) * D_ + k0 + c];
        }
        #pragma unroll
        for (int e = 0; e < 4; e++) {
            int idx = tid + e * 256; int r = idx >> 6, c = idx & 63;
            Bs[r][c] = Bw[(k0 + r) * D_ + n0 + c];
        }
        __syncthreads();
        #pragma unroll
        for (int k = 0; k < 16; k++) {
            float4 a4 = *(const float4*)&As[k][ty * 4];
            float4 b4 = *(const float4*)&Bs[k][tx * 4];
            float av[4] = {a4.x, a4.y, a4.z, a4.w};
            float bv[4] = {b4.x, b4.y, b4.z, b4.w};
            #pragma unroll
            for (int i = 0; i < 4; i++)
                #pragma unroll
                for (int j = 0; j < 4; j++) acc[i][j] += av[i] * bv[j];
        }
        __syncthreads();
    }
    #pragma unroll
    for (int i = 0; i < 4; i++)
        #pragma unroll
        for (int j = 0; j < 4; j++) {
            int m = m0 + ty * 4 + i, n = n0 + tx * 4 + j;
            int hh = n >> 6, d = n & 63;
            out[hh * (T_ * HD_) + m * HD_ + d] = acc[i][j];
        }
}

// ---------------- generic GEMM + bias + residual -----------------------------
// C[m,n] = sum_k A[m,k]B[k,n] + bias[n] + res[m,n]
__global__ void gemm_bias_res_kernel(const float* __restrict__ A, const float* __restrict__ B,
                                     const float* __restrict__ bias, const float* __restrict__ res,
                                     float* __restrict__ C, int N, int K) {
    __shared__ float As[16][68];
    __shared__ float Bs[16][64];
    float acc[4][4] = {};
    int tx = threadIdx.x, ty = threadIdx.y, tid = ty * 16 + tx;
    int m0 = blockIdx.y * 64, n0 = blockIdx.x * 64;
    for (int k0 = 0; k0 < K; k0 += 16) {
        #pragma unroll
        for (int e = 0; e < 4; e++) {
            int idx = tid + e * 256; int r = idx >> 4, c = idx & 15;
            As[c][r] = A[(m0 + r) * K + k0 + c];
        }
        #pragma unroll
        for (int e = 0; e < 4; e++) {
            int idx = tid + e * 256; int r = idx >> 6, c = idx & 63;
            Bs[r][c] = B[(k0 + r) * N + n0 + c];
        }
        __syncthreads();
        #pragma unroll
        for (int k = 0; k < 16; k++) {
            float4 a4 = *(const float4*)&As[k][ty * 4];
            float4 b4 = *(const float4*)&Bs[k][tx * 4];
            float av[4] = {a4.x, a4.y, a4.z, a4.w};
            float bv[4] = {b4.x, b4.y, b4.z, b4.w};
            #pragma unroll
            for (int i = 0; i < 4; i++)
                #pragma unroll
                for (int j = 0; j < 4; j++) acc[i][j] += av[i] * bv[j];
        }
        __syncthreads();
    }
    #pragma unroll
    for (int i = 0; i < 4; i++)
        #pragma unroll
        for (int j = 0; j < 4; j++) {
            int m = m0 + ty * 4 + i, n = n0 + tx * 4 + j;
            C[m * N + n] = acc[i][j] + bias[n] + res[m * N + n];
        }
}

// ---------------- fused SwiGLU up-projection ---------------------------------
// out[m,n] = silu(A@W1 + b1) * (A@W2 + b2); A tile loaded once for both GEMMs.
__global__ void ffn1_kernel(const float* __restrict__ A,
                            const float* __restrict__ W1, const float* __restrict__ b1,
                            const float* __restrict__ W2, const float* __restrict__ b2,
                            float* __restrict__ out) {
    __shared__ float As [16][68];
    __shared__ float B1s[16][64];
    __shared__ float B2s[16][64];
    float acc1[4][4] = {}, acc2[4][4] = {};
    int tx = threadIdx.x, ty = threadIdx.y, tid = ty * 16 + tx;
    int m0 = blockIdx.y * 64, n0 = blockIdx.x * 64;
    for (int k0 = 0; k0 < D_; k0 += 16) {
        #pragma unroll
        for (int e = 0; e < 4; e++) {
            int idx = tid + e * 256; int r = idx >> 4, c = idx & 15;
            As[c][r] = A[(m0 + r) * D_ + k0 + c];
        }
        #pragma unroll
        for (int e = 0; e < 4; e++) {
            int idx = tid + e * 256; int r = idx >> 6, c = idx & 63;
            B1s[r][c] = W1[(k0 + r) * FF_ + n0 + c];
            B2s[r][c] = W2[(k0 + r) * FF_ + n0 + c];
        }
        __syncthreads();
        #pragma unroll
        for (int k = 0; k < 16; k++) {
            float4 a4 = *(const float4*)&As[k][ty * 4];
            float4 c4 = *(const float4*)&B1s[k][tx * 4];
            float4 d4 = *(const float4*)&B2s[k][tx * 4];
            float av[4] = {a4.x, a4.y, a4.z, a4.w};
            float bv[4] = {c4.x, c4.y, c4.z, c4.w};
            float cv[4] = {d4.x, d4.y, d4.z, d4.w};
            #pragma unroll
            for (int i = 0; i < 4; i++)
                #pragma unroll
                for (int j = 0; j < 4; j++) {
                    acc1[i][j] += av[i] * bv[j];
                    acc2[i][j] += av[i] * cv[j];
                }
        }
        __syncthreads();
    }
    #pragma unroll
    for (int i = 0; i < 4; i++)
        #pragma unroll
        for (int j = 0; j < 4; j++) {
            int m = m0 + ty * 4 + i, n = n0 + tx * 4 + j;
            float a = acc1[i][j] + b1[n];
            float b = acc2[i][j] + b2[n];
            float sig = 1.f / (1.f + __expf(-a));
            out[m * FF_ + n] = (a * sig) * b;
        }
}

// ---------------- causal flash attention (fp32, 64x64 tiles) -----------------
// grid: (T_/64, H_), block 16x16. Online softmax, S/P resident in smem.
#define AP 68  // smem pitch (floats): multiple of 4 for float4, odd/32 for banks
__global__ void attn_kernel(const float* __restrict__ q, const float* __restrict__ k,
                            const float* __restrict__ v, float* __restrict__ ctx) {
    extern __shared__ float smf[];
    float* Qs   = smf;               // 64*AP
    float* Ks   = Qs + 64 * AP;      // 64*AP
    float* Vs   = Ks + 64 * AP;      // 64*AP
    float* Ss   = Vs + 64 * AP;      // 64*AP
    float* part = Ss + 64 * AP;      // 64*16
    float* m_i  = part + 64 * 16;    // 64
    float* l_i  = m_i + 64;          // 64
    float* resc = l_i + 64;          // 64

    int tx = threadIdx.x, ty = threadIdx.y, tid = ty * 16 + tx;
    int qt = blockIdx.x, h = blockIdx.y;
    int qm0 = qt * 64;
    const float* qh = q + h * (T_ * HD_);
    const float* kh = k + h * (T_ * HD_);
    const float* vh = v + h * (T_ * HD_);

    #pragma unroll
    for (int e = 0; e < 16; e++) {
        int idx = tid + e * 256; int r = idx >> 6, d = idx & 63;
        Qs[r * AP + d] = qh[(qm0 + r) * HD_ + d] * 0.125f;  // 1/sqrt(64)
    }
    if (tid < 64) { m_i[tid] = -1e30f; l_i[tid] = 0.f; }
    float acc[4][4] = {};

    for (int kt = 0; kt <= qt; kt++) {
        int km0 = kt * 64;
        __syncthreads();  // previous iter's readers of Ks/Vs/Ss done; Q/m/l init visible
        #pragma unroll
        for (int e = 0; e < 16; e++) {
            int idx = tid + e * 256; int r = idx >> 6, d = idx & 63;
            Ks[r * AP + d] = kh[(km0 + r) * HD_ + d];
            Vs[r * AP + d] = vh[(km0 + r) * HD_ + d];
        }
        __syncthreads();
        // S = Q K^T  (4x4 per thread, vectorized over d)
        float sv[4][4] = {};
        #pragma unroll
        for (int d = 0; d < 64; d += 4) {
            float qf[4][4], kf[4][4];
            #pragma unroll
            for (int i = 0; i < 4; i++) {
                float4 t = *(const float4*)&Qs[(ty * 4 + i) * AP + d];
                qf[i][0] = t.x; qf[i][1] = t.y; qf[i][2] = t.z; qf[i][3] = t.w;
            }
            #pragma unroll
            for (int j = 0; j < 4; j++) {
                float4 t = *(const float4*)&Ks[(tx * 4 + j) * AP + d];
                kf[j][0] = t.x; kf[j][1] = t.y; kf[j][2] = t.z; kf[j][3] = t.w;
            }
            #pragma unroll
            for (int i = 0; i < 4; i++)
                #pragma unroll
                for (int j = 0; j < 4; j++)
                    #pragma unroll
                    for (int c = 0; c < 4; c++) sv[i][j] += qf[i][c] * kf[j][c];
        }
        #pragma unroll
        for (int i = 0; i < 4; i++)
            #pragma unroll
            for (int j = 0; j < 4; j++) {
                int r = ty * 4 + i, c = tx * 4 + j;
                float val = sv[i][j];
                if (km0 + c > qm0 + r) val = -1e30f;  // causal mask
                Ss[r * AP + c] = val;
            }
        __syncthreads();
        if (tid < 64) {  // row max + rescale factor
            float mx = -1e30f;
            for (int c = 0; c < 64; c++) mx = fmaxf(mx, Ss[tid * AP + c]);
            float nm = fmaxf(m_i[tid], mx);
            resc[tid] = __expf(m_i[tid] - nm);
            m_i[tid] = nm;
        }
        __syncthreads();
        #pragma unroll
        for (int i = 0; i < 4; i++) {  // P = exp(S - m), partial row sums
            int r = ty * 4 + i;
            float mr = m_i[r], ps = 0.f;
            #pragma unroll
            for (int j = 0; j < 4; j++) {
                float p = __expf(Ss[r * AP + tx * 4 + j] - mr);
                Ss[r * AP + tx * 4 + j] = p;
                ps += p;
            }
            part[r * 16 + tx] = ps;
        }
        __syncthreads();
        if (tid < 64) {
            float sum = 0.f;
            for (int c = 0; c < 16; c++) sum += part[tid * 16 + c];
            l_i[tid] = l_i[tid] * resc[tid] + sum;
        }
        // O = O*rescale + P @ V
        #pragma unroll
        for (int i = 0; i < 4; i++) {
            float rs = resc[ty * 4 + i];
            #pragma unroll
            for (int j = 0; j < 4; j++) acc[i][j] *= rs;
        }
        #pragma unroll
        for (int kk = 0; kk < 64; kk += 4) {
            float pf[4][4], vf[4][4];
            #pragma unroll
            for (int i = 0; i < 4; i++) {
                float4 t = *(const float4*)&Ss[(ty * 4 + i) * AP + kk];
                pf[i][0] = t.x; pf[i][1] = t.y; pf[i][2] = t.z; pf[i][3] = t.w;
            }
            #pragma unroll
            for (int c = 0; c < 4; c++) {
                float4 t = *(const float4*)&Vs[(kk + c) * AP + tx * 4];
                vf[c][0] = t.x; vf[c][1] = t.y; vf[c][2] = t.z; vf[c][3] = t.w;
            }
            #pragma unroll
            for (int i = 0; i < 4; i++)
                #pragma unroll
                for (int j = 0; j < 4; j++)
                    #pragma unroll
                    for (int c = 0; c < 4; c++) acc[i][j] += pf[i][c] * vf[c][j];
        }
    }
    __syncthreads();  // l_i final
    #pragma unroll
    for (int i = 0; i < 4; i++) {
        int r = ty * 4 + i;
        float inv = 1.f / l_i[r];
        #pragma unroll
        for (int j = 0; j < 4; j++)
            ctx[(qm0 + r) * D_ + h * 64 + tx * 4 + j] = acc[i][j] * inv;
    }
}

// ---------------- launch -----------------------------------------------------
extern "C" void kernel_launch(void* const* d_in, const int* in_sizes, int n_in,
                              void* d_out, int out_size) {
    const float* x  = (const float*)d_in[0];
    const float* Wq = (const float*)d_in[1];
    const float* Wk = (const float*)d_in[2];
    const float* Wv = (const float*)d_in[3];
    const float* Wo = (const float*)d_in[4];
    const float* bo = (const float*)d_in[5];
    const float* w1 = (const float*)d_in[6];
    const float* b1 = (const float*)d_in[7];
    const float* w2 = (const float*)d_in[8];
    const float* b2 = (const float*)d_in[9];
    const float* w3 = (const float*)d_in[10];
    const float* b3 = (const float*)d_in[11];
    const float* g1 = (const float*)d_in[12];
    const float* s1 = (const float*)d_in[13];
    const float* g2 = (const float*)d_in[14];
    const float* s2 = (const float*)d_in[15];
    float* out = (float*)d_out;

    float *hb, *qb, *kb, *vb, *ctxb, *x2b, *ffb;
    cudaGetSymbolAddress((void**)&hb,   g_h);
    cudaGetSymbolAddress((void**)&qb,   g_q);
    cudaGetSymbolAddress((void**)&kb,   g_k);
    cudaGetSymbolAddress((void**)&vb,   g_v);
    cudaGetSymbolAddress((void**)&ctxb, g_ctx);
    cudaGetSymbolAddress((void**)&x2b,  g_x2);
    cudaGetSymbolAddress((void**)&ffb,  g_ff);

    const int attn_smem = (4 * 64 * AP + 64 * 16 + 3 * 64) * (int)sizeof(float);
    cudaFuncSetAttribute(attn_kernel, cudaFuncAttributeMaxDynamicSharedMemorySize, attn_smem);

    dim3 blk(16, 16);

    // 1. LN1
    ln_kernel<<<T_, 256>>>(x, g1, s1, hb);
    // 2. QKV (head-major outputs)
    qkv_kernel<<<dim3(D_ / 64, T_ / 64, 3), blk>>>(hb, Wq, Wk, Wv, qb, kb, vb);
    // 3. causal attention
    attn_kernel<<<dim3(T_ / 64, H_), blk, attn_smem>>>(qb, kb, vb, ctxb);
    // 4. out projection + bias + residual
    gemm_bias_res_kernel<<<dim3(D_ / 64, T_ / 64), blk>>>(ctxb, Wo, bo, x, x2b, D_, D_);
    // 5. LN2
    ln_kernel<<<T_, 256>>>(x2b, g2, s2, hb);
    // 6. SwiGLU up (fused dual GEMM)
    ffn1_kernel<<<dim3(FF_ / 64, T_ / 64), blk>>>(hb, w1, b1, w2, b2, ffb);
    // 7. down projection + bias + residual -> output
    gemm_bias_res_kernel<<<dim3(D_ / 64, T_ / 64), blk>>>(ffb, w3, b3, x2b, out, D_, FF_);
}

// round 6
// speedup vs baseline: 1.5293x; 1.5293x over previous
#include <cuda_runtime.h>
#include <math.h>

#define T_  4096
#define D_  768
#define H_  12
#define HD_ 64
#define FF_ 3072

// ---------------- scratch (device globals; no allocation allowed) ------------
__device__ float g_h  [T_ * D_];   // layernorm output
__device__ float g_q  [T_ * D_];   // head-major [H][T][HD]
__device__ float g_k  [T_ * D_];
__device__ float g_v  [T_ * D_];
__device__ float g_ctx[T_ * D_];   // attention output [T, D]
__device__ float g_x2 [T_ * D_];   // residual stream after MHA
__device__ float g_y1 [T_ * FF_];  // h@w1+b1
__device__ float g_ff [T_ * FF_];  // SwiGLU hidden

// ---------------- LayerNorm ---------------------------------------------------
__global__ void ln_kernel(const float* __restrict__ x, const float* __restrict__ g,
                          const float* __restrict__ s, float* __restrict__ out) {
    int row = blockIdx.x;
    const float* xr = x + row * D_;
    float sum = 0.f, sq = 0.f;
    for (int i = threadIdx.x; i < D_; i += 256) {
        float v = xr[i]; sum += v; sq += v * v;
    }
    __shared__ float ssum[8], ssq[8];
    #pragma unroll
    for (int o = 16; o > 0; o >>= 1) {
        sum += __shfl_down_sync(0xffffffffu, sum, o);
        sq  += __shfl_down_sync(0xffffffffu, sq,  o);
    }
    int w = threadIdx.x >> 5, l = threadIdx.x & 31;
    if (l == 0) { ssum[w] = sum; ssq[w] = sq; }
    __syncthreads();
    if (threadIdx.x == 0) {
        float a = 0.f, b = 0.f;
        #pragma unroll
        for (int i = 0; i < 8; i++) { a += ssum[i]; b += ssq[i]; }
        ssum[0] = a; ssq[0] = b;
    }
    __syncthreads();
    float mean = ssum[0] * (1.f / D_);
    float var  = ssq[0]  * (1.f / D_) - mean * mean;
    float rstd = rsqrtf(var + 1e-5f);
    for (int i = threadIdx.x; i < D_; i += 256)
        out[row * D_ + i] = g[i] * (xr[i] - mean) * rstd + s[i];
}

// ---------------- tf32 tensor-core GEMM --------------------------------------
// C[M,N] = A[M,K] @ B[K,N] (+ epilogue). 128x128x16 CTA tile, 8 warps (2x4),
// warp tile 64x32, mma.m16n8k8.tf32, cp.async double-buffered smem.
#define BM 128
#define BN 128
#define BK 16
#define APITCH 20    // As[m][k] pitch (floats) -> conflict-free fragment loads
#define BPITCH 132   // Bs[k][n] pitch (floats)

__device__ __forceinline__ unsigned cvt_tf32(float x) {
    unsigned r;
    asm("cvt.rna.tf32.f32 %0, %1;" : "=r"(r) : "f"(x));
    return r;
}

enum { EP_HEAD = 0, EP_BIASRES = 1, EP_BIAS = 2, EP_SWIGLU = 3 };

template <int MODE>
__global__ void __launch_bounds__(256, 2) tf32_gemm(
    const float* __restrict__ A, const float* __restrict__ B,
    const float* __restrict__ bias, const float* __restrict__ res,
    const float* __restrict__ aux, float* __restrict__ C,
    int N, int K)
{
    __shared__ float As[2][BM][APITCH];
    __shared__ float Bs[2][BK][BPITCH];
    int tid = threadIdx.x;
    int warp = tid >> 5, lane = tid & 31;
    int g = lane >> 2, tg = lane & 3;
    int wm = warp >> 2, wn = warp & 3;             // 2 x 4 warp grid
    int m0 = blockIdx.y * BM, n0 = blockIdx.x * BN;

    float acc[4][4][4] = {};                        // [mtile][ntile][c0..c3]
    int nk = K / BK;

    // --- async copy helpers ---
    #define CPA(buf, kt) do {                                                   \
        int k0_ = (kt) * BK;                                                    \
        _Pragma("unroll")                                                       \
        for (int e = 0; e < 2; e++) {                                           \
            int idx = tid + e * 256;                /* 512 float4 */            \
            int r_ = idx >> 2, c4_ = idx & 3;                                   \
            const float* src_ = A + (size_t)(m0 + r_) * K + k0_ + c4_ * 4;      \
            unsigned dst_ = (unsigned)__cvta_generic_to_shared(&As[buf][r_][c4_ * 4]); \
            asm volatile("cp.async.cg.shared.global [%0], [%1], 16;\n"          \
                         :: "r"(dst_), "l"(src_));                              \
        }                                                                       \
    } while (0)
    #define CPB(buf, kt) do {                                                   \
        int k0_ = (kt) * BK;                                                    \
        _Pragma("unroll")                                                       \
        for (int e = 0; e < 2; e++) {                                           \
            int idx = tid + e * 256;                                            \
            int r_ = idx >> 5, c4_ = idx & 31;                                  \
            const float* src_ = B + (size_t)(k0_ + r_) * N + n0 + c4_ * 4;      \
            unsigned dst_ = (unsigned)__cvta_generic_to_shared(&Bs[buf][r_][c4_ * 4]); \
            asm volatile("cp.async.cg.shared.global [%0], [%1], 16;\n"          \
                         :: "r"(dst_), "l"(src_));                              \
        }                                                                       \
    } while (0)

    CPA(0, 0); CPB(0, 0);
    asm volatile("cp.async.commit_group;\n");

    for (int t = 0; t < nk; t++) {
        int buf = t & 1;
        if (t + 1 < nk) {
            CPA(buf ^ 1, t + 1); CPB(buf ^ 1, t + 1);
            asm volatile("cp.async.commit_group;\n");
            asm volatile("cp.async.wait_group 1;\n");
        } else {
            asm volatile("cp.async.wait_group 0;\n");
        }
        __syncthreads();

        #pragma unroll
        for (int ks = 0; ks < 2; ks++) {
            int kb = ks * 8;
            unsigned af[4][4], bf[4][2];
            #pragma unroll
            for (int i = 0; i < 4; i++) {
                int mr = wm * 64 + i * 16 + g;
                af[i][0] = cvt_tf32(As[buf][mr    ][kb + tg]);
                af[i][1] = cvt_tf32(As[buf][mr + 8][kb + tg]);
                af[i][2] = cvt_tf32(As[buf][mr    ][kb + tg + 4]);
                af[i][3] = cvt_tf32(As[buf][mr + 8][kb + tg + 4]);
            }
            #pragma unroll
            for (int j = 0; j < 4; j++) {
                int nc = wn * 32 + j * 8 + g;
                bf[j][0] = cvt_tf32(Bs[buf][kb + tg    ][nc]);
                bf[j][1] = cvt_tf32(Bs[buf][kb + tg + 4][nc]);
            }
            #pragma unroll
            for (int i = 0; i < 4; i++)
                #pragma unroll
                for (int j = 0; j < 4; j++)
                    asm volatile(
                        "mma.sync.aligned.m16n8k8.row.col.f32.tf32.tf32.f32 "
                        "{%0,%1,%2,%3}, {%4,%5,%6,%7}, {%8,%9}, {%0,%1,%2,%3};"
                        : "+f"(acc[i][j][0]), "+f"(acc[i][j][1]),
                          "+f"(acc[i][j][2]), "+f"(acc[i][j][3])
                        : "r"(af[i][0]), "r"(af[i][1]), "r"(af[i][2]), "r"(af[i][3]),
                          "r"(bf[j][0]), "r"(bf[j][1]));
        }
        __syncthreads();
    }

    // --- epilogue ---
    #pragma unroll
    for (int i = 0; i < 4; i++) {
        int rbase = m0 + wm * 64 + i * 16 + g;
        #pragma unroll
        for (int j = 0; j < 4; j++) {
            int cbase = n0 + wn * 32 + j * 8 + tg * 2;
            #pragma unroll
            for (int hh = 0; hh < 2; hh++) {
                int rr = rbase + hh * 8;
                #pragma unroll
                for (int cc = 0; cc < 2; cc++) {
                    int nn = cbase + cc;
                    float v = acc[i][j][hh * 2 + cc];
                    if (MODE == EP_HEAD) {
                        // scatter to head-major [H][T][64]
                        C[(size_t)((nn >> 6) * T_ + rr) * 64 + (nn & 63)] = v;
                    } else if (MODE == EP_BIASRES) {
                        C[(size_t)rr * N + nn] = v + bias[nn] + res[(size_t)rr * N + nn];
                    } else if (MODE == EP_BIAS) {
                        C[(size_t)rr * N + nn] = v + bias[nn];
                    } else { // EP_SWIGLU: out = silu(aux) * (acc + bias)
                        float a = aux[(size_t)rr * N + nn];
                        float sig = 1.f / (1.f + __expf(-a));
                        C[(size_t)rr * N + nn] = (a * sig) * (v + bias[nn]);
                    }
                }
            }
        }
    }
    #undef CPA
    #undef CPB
}

// ---------------- causal flash attention (fp32, 64x64 tiles) -----------------
#define AP 68
__global__ void attn_kernel(const float* __restrict__ q, const float* __restrict__ k,
                            const float* __restrict__ v, float* __restrict__ ctx) {
    extern __shared__ float smf[];
    float* Qs   = smf;
    float* Ks   = Qs + 64 * AP;
    float* Vs   = Ks + 64 * AP;
    float* Ss   = Vs + 64 * AP;
    float* part = Ss + 64 * AP;
    float* m_i  = part + 64 * 16;
    float* l_i  = m_i + 64;
    float* resc = l_i + 64;

    int tx = threadIdx.x, ty = threadIdx.y, tid = ty * 16 + tx;
    int qt = blockIdx.x, h = blockIdx.y;
    int qm0 = qt * 64;
    const float* qh = q + h * (T_ * HD_);
    const float* kh = k + h * (T_ * HD_);
    const float* vh = v + h * (T_ * HD_);

    #pragma unroll
    for (int e = 0; e < 16; e++) {
        int idx = tid + e * 256; int r = idx >> 6, d = idx & 63;
        Qs[r * AP + d] = qh[(qm0 + r) * HD_ + d] * 0.125f;
    }
    if (tid < 64) { m_i[tid] = -1e30f; l_i[tid] = 0.f; }
    float acc[4][4] = {};

    for (int kt = 0; kt <= qt; kt++) {
        int km0 = kt * 64;
        __syncthreads();
        #pragma unroll
        for (int e = 0; e < 16; e++) {
            int idx = tid + e * 256; int r = idx >> 6, d = idx & 63;
            Ks[r * AP + d] = kh[(km0 + r) * HD_ + d];
            Vs[r * AP + d] = vh[(km0 + r) * HD_ + d];
        }
        __syncthreads();
        float sv[4][4] = {};
        #pragma unroll
        for (int d = 0; d < 64; d += 4) {
            float qf[4][4], kf[4][4];
            #pragma unroll
            for (int i = 0; i < 4; i++) {
                float4 t = *(const float4*)&Qs[(ty * 4 + i) * AP + d];
                qf[i][0] = t.x; qf[i][1] = t.y; qf[i][2] = t.z; qf[i][3] = t.w;
            }
            #pragma unroll
            for (int j = 0; j < 4; j++) {
                float4 t = *(const float4*)&Ks[(tx * 4 + j) * AP + d];
                kf[j][0] = t.x; kf[j][1] = t.y; kf[j][2] = t.z; kf[j][3] = t.w;
            }
            #pragma unroll
            for (int i = 0; i < 4; i++)
                #pragma unroll
                for (int j = 0; j < 4; j++)
                    #pragma unroll
                    for (int c = 0; c < 4; c++) sv[i][j] += qf[i][c] * kf[j][c];
        }
        #pragma unroll
        for (int i = 0; i < 4; i++)
            #pragma unroll
            for (int j = 0; j < 4; j++) {
                int r = ty * 4 + i, c = tx * 4 + j;
                float val = sv[i][j];
                if (km0 + c > qm0 + r) val = -1e30f;
                Ss[r * AP + c] = val;
            }
        __syncthreads();
        if (tid < 64) {
            float mx = -1e30f;
            for (int c = 0; c < 64; c++) mx = fmaxf(mx, Ss[tid * AP + c]);
            float nm = fmaxf(m_i[tid], mx);
            resc[tid] = __expf(m_i[tid] - nm);
            m_i[tid] = nm;
        }
        __syncthreads();
        #pragma unroll
        for (int i = 0; i < 4; i++) {
            int r = ty * 4 + i;
            float mr = m_i[r], ps = 0.f;
            #pragma unroll
            for (int j = 0; j < 4; j++) {
                float p = __expf(Ss[r * AP + tx * 4 + j] - mr);
                Ss[r * AP + tx * 4 + j] = p;
                ps += p;
            }
            part[r * 16 + tx] = ps;
        }
        __syncthreads();
        if (tid < 64) {
            float sum = 0.f;
            for (int c = 0; c < 16; c++) sum += part[tid * 16 + c];
            l_i[tid] = l_i[tid] * resc[tid] + sum;
        }
        #pragma unroll
        for (int i = 0; i < 4; i++) {
            float rs = resc[ty * 4 + i];
            #pragma unroll
            for (int j = 0; j < 4; j++) acc[i][j] *= rs;
        }
        #pragma unroll
        for (int kk = 0; kk < 64; kk += 4) {
            float pf[4][4], vf[4][4];
            #pragma unroll
            for (int i = 0; i < 4; i++) {
                float4 t = *(const float4*)&Ss[(ty * 4 + i) * AP + kk];
                pf[i][0] = t.x; pf[i][1] = t.y; pf[i][2] = t.z; pf[i][3] = t.w;
            }
            #pragma unroll
            for (int c = 0; c < 4; c++) {
                float4 t = *(const float4*)&Vs[(kk + c) * AP + tx * 4];
                vf[c][0] = t.x; vf[c][1] = t.y; vf[c][2] = t.z; vf[c][3] = t.w;
            }
            #pragma unroll
            for (int i = 0; i < 4; i++)
                #pragma unroll
                for (int j = 0; j < 4; j++)
                    #pragma unroll
                    for (int c = 0; c < 4; c++) acc[i][j] += pf[i][c] * vf[c][j];
        }
    }
    __syncthreads();
    #pragma unroll
    for (int i = 0; i < 4; i++) {
        int r = ty * 4 + i;
        float inv = 1.f / l_i[r];
        #pragma unroll
        for (int j = 0; j < 4; j++)
            ctx[(qm0 + r) * D_ + h * 64 + tx * 4 + j] = acc[i][j] * inv;
    }
}

// ---------------- launch -----------------------------------------------------
extern "C" void kernel_launch(void* const* d_in, const int* in_sizes, int n_in,
                              void* d_out, int out_size) {
    const float* x  = (const float*)d_in[0];
    const float* Wq = (const float*)d_in[1];
    const float* Wk = (const float*)d_in[2];
    const float* Wv = (const float*)d_in[3];
    const float* Wo = (const float*)d_in[4];
    const float* bo = (const float*)d_in[5];
    const float* w1 = (const float*)d_in[6];
    const float* b1 = (const float*)d_in[7];
    const float* w2 = (const float*)d_in[8];
    const float* b2 = (const float*)d_in[9];
    const float* w3 = (const float*)d_in[10];
    const float* b3 = (const float*)d_in[11];
    const float* g1 = (const float*)d_in[12];
    const float* s1 = (const float*)d_in[13];
    const float* g2 = (const float*)d_in[14];
    const float* s2 = (const float*)d_in[15];
    float* out = (float*)d_out;

    float *hb, *qb, *kb, *vb, *ctxb, *x2b, *y1b, *ffb;
    cudaGetSymbolAddress((void**)&hb,   g_h);
    cudaGetSymbolAddress((void**)&qb,   g_q);
    cudaGetSymbolAddress((void**)&kb,   g_k);
    cudaGetSymbolAddress((void**)&vb,   g_v);
    cudaGetSymbolAddress((void**)&ctxb, g_ctx);
    cudaGetSymbolAddress((void**)&x2b,  g_x2);
    cudaGetSymbolAddress((void**)&y1b,  g_y1);
    cudaGetSymbolAddress((void**)&ffb,  g_ff);

    const int attn_smem = (4 * 64 * AP + 64 * 16 + 3 * 64) * (int)sizeof(float);
    cudaFuncSetAttribute(attn_kernel, cudaFuncAttributeMaxDynamicSharedMemorySize, attn_smem);

    dim3 gD(D_ / BN, T_ / BM);     // (6, 32)
    dim3 gF(FF_ / BN, T_ / BM);    // (24, 32)

    // 1. LN1
    ln_kernel<<<T_, 256>>>(x, g1, s1, hb);
    // 2. QKV projections (head-major outputs)
    tf32_gemm<EP_HEAD><<<gD, 256>>>(hb, Wq, nullptr, nullptr, nullptr, qb, D_, D_);
    tf32_gemm<EP_HEAD><<<gD, 256>>>(hb, Wk, nullptr, nullptr, nullptr, kb, D_, D_);
    tf32_gemm<EP_HEAD><<<gD, 256>>>(hb, Wv, nullptr, nullptr, nullptr, vb, D_, D_);
    // 3. causal attention
    attn_kernel<<<dim3(T_ / 64, H_), dim3(16, 16), attn_smem>>>(qb, kb, vb, ctxb);
    // 4. out projection + bias + residual
    tf32_gemm<EP_BIASRES><<<gD, 256>>>(ctxb, Wo, bo, x, nullptr, x2b, D_, D_);
    // 5. LN2
    ln_kernel<<<T_, 256>>>(x2b, g2, s2, hb);
    // 6. SwiGLU: y1 = h@w1+b1 ; ff = silu(y1) * (h@w2+b2)
    tf32_gemm<EP_BIAS>  <<<gF, 256>>>(hb, w1, b1, nullptr, nullptr, y1b, FF_, D_);
    tf32_gemm<EP_SWIGLU><<<gF, 256>>>(hb, w2, b2, nullptr, y1b, ffb, FF_, D_);
    // 7. down projection + bias + residual -> output
    tf32_gemm<EP_BIASRES><<<gD, 256>>>(ffb, w3, b3, x2b, nullptr, out, D_, FF_);
}

// round 8
// speedup vs baseline: 2.9964x; 1.9593x over previous
#include <cuda_runtime.h>
#include <math.h>

#define T_  4096
#define D_  768
#define H_  12
#define HD_ 64
#define FF_ 3072

// ---------------- scratch (device globals; no allocation allowed) ------------
__device__ float g_h  [T_ * D_];   // layernorm output
__device__ float g_q  [T_ * D_];   // head-major [H][T][HD]
__device__ float g_k  [T_ * D_];
__device__ float g_v  [T_ * D_];
__device__ float g_ctx[T_ * D_];   // attention output [T, D]
__device__ float g_x2 [T_ * D_];   // residual stream after MHA
__device__ float g_y1 [T_ * FF_];  // h@w1+b1
__device__ float g_ff [T_ * FF_];  // SwiGLU hidden

// ---------------- LayerNorm ---------------------------------------------------
__global__ void ln_kernel(const float* __restrict__ x, const float* __restrict__ g,
                          const float* __restrict__ s, float* __restrict__ out) {
    int row = blockIdx.x;
    const float* xr = x + row * D_;
    float sum = 0.f, sq = 0.f;
    for (int i = threadIdx.x; i < D_; i += 256) {
        float v = xr[i]; sum += v; sq += v * v;
    }
    __shared__ float ssum[8], ssq[8];
    #pragma unroll
    for (int o = 16; o > 0; o >>= 1) {
        sum += __shfl_down_sync(0xffffffffu, sum, o);
        sq  += __shfl_down_sync(0xffffffffu, sq,  o);
    }
    int w = threadIdx.x >> 5, l = threadIdx.x & 31;
    if (l == 0) { ssum[w] = sum; ssq[w] = sq; }
    __syncthreads();
    if (threadIdx.x == 0) {
        float a = 0.f, b = 0.f;
        #pragma unroll
        for (int i = 0; i < 8; i++) { a += ssum[i]; b += ssq[i]; }
        ssum[0] = a; ssq[0] = b;
    }
    __syncthreads();
    float mean = ssum[0] * (1.f / D_);
    float var  = ssq[0]  * (1.f / D_) - mean * mean;
    float rstd = rsqrtf(var + 1e-5f);
    for (int i = threadIdx.x; i < D_; i += 256)
        out[row * D_ + i] = g[i] * (xr[i] - mean) * rstd + s[i];
}

// ---------------- tf32 helpers ------------------------------------------------
__device__ __forceinline__ unsigned cvt_tf32(float x) {
    unsigned r;
    asm("cvt.rna.tf32.f32 %0, %1;" : "=r"(r) : "f"(x));
    return r;
}

#define MMA_TF32(acc, a0, a1, a2, a3, b0, b1)                                   \
    asm volatile(                                                               \
        "mma.sync.aligned.m16n8k8.row.col.f32.tf32.tf32.f32 "                   \
        "{%0,%1,%2,%3}, {%4,%5,%6,%7}, {%8,%9}, {%0,%1,%2,%3};"                 \
        : "+f"((acc)[0]), "+f"((acc)[1]), "+f"((acc)[2]), "+f"((acc)[3])        \
        : "r"(a0), "r"(a1), "r"(a2), "r"(a3), "r"(b0), "r"(b1))

// ---------------- tf32 tensor-core GEMM --------------------------------------
#define BM 128
#define BN 128
#define BK 16
#define APITCH 20
#define BPITCH 132

enum { EP_HEAD = 0, EP_BIASRES = 1, EP_BIAS = 2, EP_SWIGLU = 3 };

template <int MODE>
__global__ void __launch_bounds__(256, 2) tf32_gemm(
    const float* __restrict__ A, const float* __restrict__ B,
    const float* __restrict__ bias, const float* __restrict__ res,
    const float* __restrict__ aux, float* __restrict__ C,
    int N, int K)
{
    __shared__ float As[2][BM][APITCH];
    __shared__ float Bs[2][BK][BPITCH];
    int tid = threadIdx.x;
    int warp = tid >> 5, lane = tid & 31;
    int g = lane >> 2, tg = lane & 3;
    int wm = warp >> 2, wn = warp & 3;
    int m0 = blockIdx.y * BM, n0 = blockIdx.x * BN;

    float acc[4][4][4] = {};
    int nk = K / BK;

    #define CPA(buf, kt) do {                                                   \
        int k0_ = (kt) * BK;                                                    \
        _Pragma("unroll")                                                       \
        for (int e = 0; e < 2; e++) {                                           \
            int idx = tid + e * 256;                                            \
            int r_ = idx >> 2, c4_ = idx & 3;                                   \
            const float* src_ = A + (size_t)(m0 + r_) * K + k0_ + c4_ * 4;      \
            unsigned dst_ = (unsigned)__cvta_generic_to_shared(&As[buf][r_][c4_ * 4]); \
            asm volatile("cp.async.cg.shared.global [%0], [%1], 16;\n"          \
                         :: "r"(dst_), "l"(src_));                              \
        }                                                                       \
    } while (0)
    #define CPB(buf, kt) do {                                                   \
        int k0_ = (kt) * BK;                                                    \
        _Pragma("unroll")                                                       \
        for (int e = 0; e < 2; e++) {                                           \
            int idx = tid + e * 256;                                            \
            int r_ = idx >> 5, c4_ = idx & 31;                                  \
            const float* src_ = B + (size_t)(k0_ + r_) * N + n0 + c4_ * 4;      \
            unsigned dst_ = (unsigned)__cvta_generic_to_shared(&Bs[buf][r_][c4_ * 4]); \
            asm volatile("cp.async.cg.shared.global [%0], [%1], 16;\n"          \
                         :: "r"(dst_), "l"(src_));                              \
        }                                                                       \
    } while (0)

    CPA(0, 0); CPB(0, 0);
    asm volatile("cp.async.commit_group;\n");

    for (int t = 0; t < nk; t++) {
        int buf = t & 1;
        if (t + 1 < nk) {
            CPA(buf ^ 1, t + 1); CPB(buf ^ 1, t + 1);
            asm volatile("cp.async.commit_group;\n");
            asm volatile("cp.async.wait_group 1;\n");
        } else {
            asm volatile("cp.async.wait_group 0;\n");
        }
        __syncthreads();

        #pragma unroll
        for (int ks = 0; ks < 2; ks++) {
            int kb = ks * 8;
            unsigned af[4][4], bf[4][2];
            #pragma unroll
            for (int i = 0; i < 4; i++) {
                int mr = wm * 64 + i * 16 + g;
                af[i][0] = cvt_tf32(As[buf][mr    ][kb + tg]);
                af[i][1] = cvt_tf32(As[buf][mr + 8][kb + tg]);
                af[i][2] = cvt_tf32(As[buf][mr    ][kb + tg + 4]);
                af[i][3] = cvt_tf32(As[buf][mr + 8][kb + tg + 4]);
            }
            #pragma unroll
            for (int j = 0; j < 4; j++) {
                int nc = wn * 32 + j * 8 + g;
                bf[j][0] = cvt_tf32(Bs[buf][kb + tg    ][nc]);
                bf[j][1] = cvt_tf32(Bs[buf][kb + tg + 4][nc]);
            }
            #pragma unroll
            for (int i = 0; i < 4; i++)
                #pragma unroll
                for (int j = 0; j < 4; j++)
                    MMA_TF32(acc[i][j], af[i][0], af[i][1], af[i][2], af[i][3],
                             bf[j][0], bf[j][1]);
        }
        __syncthreads();
    }

    #pragma unroll
    for (int i = 0; i < 4; i++) {
        int rbase = m0 + wm * 64 + i * 16 + g;
        #pragma unroll
        for (int j = 0; j < 4; j++) {
            int cbase = n0 + wn * 32 + j * 8 + tg * 2;
            #pragma unroll
            for (int hh = 0; hh < 2; hh++) {
                int rr = rbase + hh * 8;
                #pragma unroll
                for (int cc = 0; cc < 2; cc++) {
                    int nn = cbase + cc;
                    float v = acc[i][j][hh * 2 + cc];
                    if (MODE == EP_HEAD) {
                        C[(size_t)((nn >> 6) * T_ + rr) * 64 + (nn & 63)] = v;
                    } else if (MODE == EP_BIASRES) {
                        C[(size_t)rr * N + nn] = v + bias[nn] + res[(size_t)rr * N + nn];
                    } else if (MODE == EP_BIAS) {
                        C[(size_t)rr * N + nn] = v + bias[nn];
                    } else {
                        float a = aux[(size_t)rr * N + nn];
                        float sig = 1.f / (1.f + __expf(-a));
                        C[(size_t)rr * N + nn] = (a * sig) * (v + bias[nn]);
                    }
                }
            }
        }
    }
    #undef CPA
    #undef CPB
}

// ---------------- causal flash attention, tf32 MMA ---------------------------
// Q tile 128 rows x 8 warps (16 rows/warp), K/V tiles 64 x 64. Online softmax
// in registers (each thread owns rows g and g+8 across all n-tiles).
#define FAP 68   // smem pitch

__global__ void __launch_bounds__(256) attn_mma_kernel(
    const float* __restrict__ q, const float* __restrict__ k,
    const float* __restrict__ v, float* __restrict__ ctx)
{
    extern __shared__ float sm[];
    float* Ks = sm;                  // [64][FAP]
    float* Vs = Ks + 64 * FAP;       // [64][FAP]
    float* Ps = Vs + 64 * FAP;       // [128][FAP]

    int tid = threadIdx.x;
    int warp = tid >> 5, lane = tid & 31;
    int g = lane >> 2, tg = lane & 3;
    int qt = gridDim.x - 1 - blockIdx.x;  // big tiles first (wave balance)
    int h = blockIdx.y;
    int qm0 = qt * 128;
    const float* qh = q + h * (T_ * HD_);
    const float* kh = k + h * (T_ * HD_);
    const float* vh = v + h * (T_ * HD_);

    int r0 = qm0 + warp * 16 + g;    // this thread's two global rows
    int r1 = r0 + 8;

    // Q fragments in registers (scaled by 1/sqrt(64)); layout validated by GEMM
    unsigned qf[8][4];
    #pragma unroll
    for (int kc = 0; kc < 8; kc++) {
        qf[kc][0] = cvt_tf32(qh[(size_t)r0 * 64 + kc * 8 + tg    ] * 0.125f);
        qf[kc][1] = cvt_tf32(qh[(size_t)r1 * 64 + kc * 8 + tg    ] * 0.125f);
        qf[kc][2] = cvt_tf32(qh[(size_t)r0 * 64 + kc * 8 + tg + 4] * 0.125f);
        qf[kc][3] = cvt_tf32(qh[(size_t)r1 * 64 + kc * 8 + tg + 4] * 0.125f);
    }

    float oacc[8][4] = {};
    float m0 = -1e30f, m1 = -1e30f, l0 = 0.f, l1 = 0.f;
    int nkt = 2 * qt + 2;

    for (int kt = 0; kt < nkt; kt++) {
        int km0 = kt * 64;
        __syncthreads();  // all warps done reading Ks/Vs from previous tile
        #pragma unroll
        for (int e = 0; e < 4; e++) {          // 1024 float4 = 64x64 each
            int idx = tid + e * 256;
            int r = idx >> 4, d4 = (idx & 15) * 4;
            *(float4*)&Ks[r * FAP + d4] = *(const float4*)&kh[(size_t)(km0 + r) * 64 + d4];
            *(float4*)&Vs[r * FAP + d4] = *(const float4*)&vh[(size_t)(km0 + r) * 64 + d4];
        }
        __syncthreads();

        // ---- S = Q K^T ----
        float sacc[8][4] = {};
        #pragma unroll
        for (int kc = 0; kc < 8; kc++) {
            #pragma unroll
            for (int j = 0; j < 8; j++) {
                unsigned b0 = cvt_tf32(Ks[(j * 8 + g) * FAP + kc * 8 + tg    ]);
                unsigned b1 = cvt_tf32(Ks[(j * 8 + g) * FAP + kc * 8 + tg + 4]);
                MMA_TF32(sacc[j], qf[kc][0], qf[kc][1], qf[kc][2], qf[kc][3], b0, b1);
            }
        }

        // ---- causal mask (only tiles touching the diagonal of this warp) ----
        if (km0 + 63 > qm0 + warp * 16) {
            #pragma unroll
            for (int j = 0; j < 8; j++) {
                int c0 = km0 + j * 8 + tg * 2, c1 = c0 + 1;
                if (c0 > r0) sacc[j][0] = -1e30f;
                if (c1 > r0) sacc[j][1] = -1e30f;
                if (c0 > r1) sacc[j][2] = -1e30f;
                if (c1 > r1) sacc[j][3] = -1e30f;
            }
        }

        // ---- online softmax (rows g / g+8; reduce across quad tg) ----
        float t0 = -1e30f, t1 = -1e30f;
        #pragma unroll
        for (int j = 0; j < 8; j++) {
            t0 = fmaxf(t0, fmaxf(sacc[j][0], sacc[j][1]));
            t1 = fmaxf(t1, fmaxf(sacc[j][2], sacc[j][3]));
        }
        t0 = fmaxf(t0, __shfl_xor_sync(0xffffffffu, t0, 1));
        t0 = fmaxf(t0, __shfl_xor_sync(0xffffffffu, t0, 2));
        t1 = fmaxf(t1, __shfl_xor_sync(0xffffffffu, t1, 1));
        t1 = fmaxf(t1, __shfl_xor_sync(0xffffffffu, t1, 2));
        float nm0 = fmaxf(m0, t0), nm1 = fmaxf(m1, t1);
        float rs0 = __expf(m0 - nm0), rs1 = __expf(m1 - nm1);
        m0 = nm0; m1 = nm1;

        int pr0 = (warp * 16 + g) * FAP, pr1 = pr0 + 8 * FAP;
        float sum0 = 0.f, sum1 = 0.f;
        #pragma unroll
        for (int j = 0; j < 8; j++) {
            float p00 = __expf(sacc[j][0] - m0);
            float p01 = __expf(sacc[j][1] - m0);
            float p10 = __expf(sacc[j][2] - m1);
            float p11 = __expf(sacc[j][3] - m1);
            sum0 += p00 + p01; sum1 += p10 + p11;
            int c = j * 8 + tg * 2;
            Ps[pr0 + c] = p00; Ps[pr0 + c + 1] = p01;
            Ps[pr1 + c] = p10; Ps[pr1 + c + 1] = p11;
        }
        l0 = l0 * rs0 + sum0;   // quad-partial; reduced at the end
        l1 = l1 * rs1 + sum1;
        #pragma unroll
        for (int j = 0; j < 8; j++) {
            oacc[j][0] *= rs0; oacc[j][1] *= rs0;
            oacc[j][2] *= rs1; oacc[j][3] *= rs1;
        }
        __syncwarp();  // Ps writes visible within warp (warp-private rows)

        // ---- O += P V ----
        #pragma unroll
        for (int kc = 0; kc < 8; kc++) {
            unsigned a0 = cvt_tf32(Ps[pr0 + kc * 8 + tg    ]);
            unsigned a1 = cvt_tf32(Ps[pr1 + kc * 8 + tg    ]);
            unsigned a2 = cvt_tf32(Ps[pr0 + kc * 8 + tg + 4]);
            unsigned a3 = cvt_tf32(Ps[pr1 + kc * 8 + tg + 4]);
            #pragma unroll
            for (int j = 0; j < 8; j++) {
                unsigned b0 = cvt_tf32(Vs[(kc * 8 + tg    ) * FAP + j * 8 + g]);
                unsigned b1 = cvt_tf32(Vs[(kc * 8 + tg + 4) * FAP + j * 8 + g]);
                MMA_TF32(oacc[j], a0, a1, a2, a3, b0, b1);
            }
        }
        __syncwarp();  // PV reads of Ps done before next tile rewrites
    }

    // ---- finalize ----
    l0 += __shfl_xor_sync(0xffffffffu, l0, 1);
    l0 += __shfl_xor_sync(0xffffffffu, l0, 2);
    l1 += __shfl_xor_sync(0xffffffffu, l1, 1);
    l1 += __shfl_xor_sync(0xffffffffu, l1, 2);
    float inv0 = 1.f / l0, inv1 = 1.f / l1;
    #pragma unroll
    for (int j = 0; j < 8; j++) {
        int col = h * 64 + j * 8 + tg * 2;
        ctx[(size_t)r0 * D_ + col    ] = oacc[j][0] * inv0;
        ctx[(size_t)r0 * D_ + col + 1] = oacc[j][1] * inv0;
        ctx[(size_t)r1 * D_ + col    ] = oacc[j][2] * inv1;
        ctx[(size_t)r1 * D_ + col + 1] = oacc[j][3] * inv1;
    }
}

// ---------------- launch -----------------------------------------------------
extern "C" void kernel_launch(void* const* d_in, const int* in_sizes, int n_in,
                              void* d_out, int out_size) {
    const float* x  = (const float*)d_in[0];
    const float* Wq = (const float*)d_in[1];
    const float* Wk = (const float*)d_in[2];
    const float* Wv = (const float*)d_in[3];
    const float* Wo = (const float*)d_in[4];
    const float* bo = (const float*)d_in[5];
    const float* w1 = (const float*)d_in[6];
    const float* b1 = (const float*)d_in[7];
    const float* w2 = (const float*)d_in[8];
    const float* b2 = (const float*)d_in[9];
    const float* w3 = (const float*)d_in[10];
    const float* b3 = (const float*)d_in[11];
    const float* g1 = (const float*)d_in[12];
    const float* s1 = (const float*)d_in[13];
    const float* g2 = (const float*)d_in[14];
    const float* s2 = (const float*)d_in[15];
    float* out = (float*)d_out;

    float *hb, *qb, *kb, *vb, *ctxb, *x2b, *y1b, *ffb;
    cudaGetSymbolAddress((void**)&hb,   g_h);
    cudaGetSymbolAddress((void**)&qb,   g_q);
    cudaGetSymbolAddress((void**)&kb,   g_k);
    cudaGetSymbolAddress((void**)&vb,   g_v);
    cudaGetSymbolAddress((void**)&ctxb, g_ctx);
    cudaGetSymbolAddress((void**)&x2b,  g_x2);
    cudaGetSymbolAddress((void**)&y1b,  g_y1);
    cudaGetSymbolAddress((void**)&ffb,  g_ff);

    const int attn_smem = (64 * FAP + 64 * FAP + 128 * FAP) * (int)sizeof(float);
    cudaFuncSetAttribute(attn_mma_kernel, cudaFuncAttributeMaxDynamicSharedMemorySize, attn_smem);

    dim3 gD(D_ / BN, T_ / BM);     // (6, 32)
    dim3 gF(FF_ / BN, T_ / BM);    // (24, 32)

    // 1. LN1
    ln_kernel<<<T_, 256>>>(x, g1, s1, hb);
    // 2. QKV projections (head-major outputs)
    tf32_gemm<EP_HEAD><<<gD, 256>>>(hb, Wq, nullptr, nullptr, nullptr, qb, D_, D_);
    tf32_gemm<EP_HEAD><<<gD, 256>>>(hb, Wk, nullptr, nullptr, nullptr, kb, D_, D_);
    tf32_gemm<EP_HEAD><<<gD, 256>>>(hb, Wv, nullptr, nullptr, nullptr, vb, D_, D_);
    // 3. causal attention (tf32 MMA)
    attn_mma_kernel<<<dim3(T_ / 128, H_), 256, attn_smem>>>(qb, kb, vb, ctxb);
    // 4. out projection + bias + residual
    tf32_gemm<EP_BIASRES><<<gD, 256>>>(ctxb, Wo, bo, x, nullptr, x2b, D_, D_);
    // 5. LN2
    ln_kernel<<<T_, 256>>>(x2b, g2, s2, hb);
    // 6. SwiGLU: y1 = h@w1+b1 ; ff = silu(y1) * (h@w2+b2)
    tf32_gemm<EP_BIAS>  <<<gF, 256>>>(hb, w1, b1, nullptr, nullptr, y1b, FF_, D_);
    tf32_gemm<EP_SWIGLU><<<gF, 256>>>(hb, w2, b2, nullptr, y1b, ffb, FF_, D_);
    // 7. down projection + bias + residual -> output
    tf32_gemm<EP_BIASRES><<<gD, 256>>>(ffb, w3, b3, x2b, nullptr, out, D_, FF_);
}

// round 9
// speedup vs baseline: 4.1563x; 1.3871x over previous
#include <cuda_runtime.h>
#include <cuda_bf16.h>
#include <math.h>

#define T_  4096
#define D_  768
#define H_  12
#define HD_ 64
#define FF_ 3072

// ---------------- scratch (device globals; no allocation allowed) ------------
__device__ __nv_bfloat16 g_hb  [T_ * D_];        // LN output (bf16, GEMM A)
__device__ float         g_qkv [3 * T_ * D_];    // head-major q|k|v fp32
__device__ __nv_bfloat16 g_ctxb[T_ * D_];        // attention out (bf16, GEMM A)
__device__ float         g_x2  [T_ * D_];        // residual after MHA
__device__ float         g_y1  [T_ * FF_];       // h@w1+b1 (fp32)
__device__ __nv_bfloat16 g_ffb [T_ * FF_];       // SwiGLU hidden (bf16, GEMM A)
// weights: bf16, transposed to [n][k]
__device__ __nv_bfloat16 g_Wqb[D_ * D_];
__device__ __nv_bfloat16 g_Wkb[D_ * D_];
__device__ __nv_bfloat16 g_Wvb[D_ * D_];
__device__ __nv_bfloat16 g_Wob[D_ * D_];
__device__ __nv_bfloat16 g_w1b[D_ * FF_];
__device__ __nv_bfloat16 g_w2b[D_ * FF_];
__device__ __nv_bfloat16 g_w3b[FF_ * D_];

// ---------------- weight convert + transpose: fp32 [K][N] -> bf16 [N][K] -----
__global__ void wconv_kernel(const float* __restrict__ W, __nv_bfloat16* __restrict__ out,
                             int K, int N) {
    __shared__ float tile[32][33];
    int n0 = blockIdx.x * 32, k0 = blockIdx.y * 32;
    int tx = threadIdx.x, ty = threadIdx.y;    // 32 x 8
    #pragma unroll
    for (int e = 0; e < 4; e++)
        tile[ty + e * 8][tx] = W[(size_t)(k0 + ty + e * 8) * N + n0 + tx];
    __syncthreads();
    #pragma unroll
    for (int e = 0; e < 4; e++)
        out[(size_t)(n0 + ty + e * 8) * K + k0 + tx] = __float2bfloat16(tile[tx][ty + e * 8]);
}

// ---------------- LayerNorm (bf16 output) ------------------------------------
__global__ void ln_kernel(const float* __restrict__ x, const float* __restrict__ g,
                          const float* __restrict__ s, __nv_bfloat16* __restrict__ out) {
    int row = blockIdx.x;
    const float* xr = x + (size_t)row * D_;
    float sum = 0.f, sq = 0.f;
    for (int i = threadIdx.x; i < D_; i += 256) {
        float v = xr[i]; sum += v; sq += v * v;
    }
    __shared__ float ssum[8], ssq[8];
    #pragma unroll
    for (int o = 16; o > 0; o >>= 1) {
        sum += __shfl_down_sync(0xffffffffu, sum, o);
        sq  += __shfl_down_sync(0xffffffffu, sq,  o);
    }
    int w = threadIdx.x >> 5, l = threadIdx.x & 31;
    if (l == 0) { ssum[w] = sum; ssq[w] = sq; }
    __syncthreads();
    if (threadIdx.x == 0) {
        float a = 0.f, b = 0.f;
        #pragma unroll
        for (int i = 0; i < 8; i++) { a += ssum[i]; b += ssq[i]; }
        ssum[0] = a; ssq[0] = b;
    }
    __syncthreads();
    float mean = ssum[0] * (1.f / D_);
    float var  = ssq[0]  * (1.f / D_) - mean * mean;
    float rstd = rsqrtf(var + 1e-5f);
    for (int i = threadIdx.x; i < D_; i += 256)
        out[(size_t)row * D_ + i] = __float2bfloat16(g[i] * (xr[i] - mean) * rstd + s[i]);
}

// ---------------- helpers ------------------------------------------------------
__device__ __forceinline__ unsigned cvt_tf32(float x) {
    unsigned r;
    asm("cvt.rna.tf32.f32 %0, %1;" : "=r"(r) : "f"(x));
    return r;
}

#define MMA_TF32(acc, a0, a1, a2, a3, b0, b1)                                   \
    asm volatile(                                                               \
        "mma.sync.aligned.m16n8k8.row.col.f32.tf32.tf32.f32 "                   \
        "{%0,%1,%2,%3}, {%4,%5,%6,%7}, {%8,%9}, {%0,%1,%2,%3};"                 \
        : "+f"((acc)[0]), "+f"((acc)[1]), "+f"((acc)[2]), "+f"((acc)[3])        \
        : "r"(a0), "r"(a1), "r"(a2), "r"(a3), "r"(b0), "r"(b1))

#define MMA_BF16(acc, a0, a1, a2, a3, b0, b1)                                   \
    asm volatile(                                                               \
        "mma.sync.aligned.m16n8k16.row.col.f32.bf16.bf16.f32 "                  \
        "{%0,%1,%2,%3}, {%4,%5,%6,%7}, {%8,%9}, {%0,%1,%2,%3};"                 \
        : "+f"((acc)[0]), "+f"((acc)[1]), "+f"((acc)[2]), "+f"((acc)[3])        \
        : "r"(a0), "r"(a1), "r"(a2), "r"(a3), "r"(b0), "r"(b1))

// ---------------- bf16 tensor-core GEMM --------------------------------------
// C[M,N] = A[M,K] @ Bt[N,K]^T. 128x128x32 CTA tile, 8 warps (2x4), warp tile
// 64x32, mma.m16n8k16.bf16 with fp32 accumulate. A [m][k] bf16, B [n][k] bf16.
#define BM 128
#define BN 128
#define HKB 32      // bf16 k per tile
#define HP  40      // smem pitch in bf16 (80B = 20 words; conflict-free)

enum { EP_HEAD = 0, EP_BIASRES = 1, EP_BIAS = 2, EP_SWIGLU = 3 };

template <int MODE>
__global__ void __launch_bounds__(256, 2) bf16_gemm(
    const __nv_bfloat16* __restrict__ A,  const __nv_bfloat16* __restrict__ B,
    const __nv_bfloat16* __restrict__ B1, const __nv_bfloat16* __restrict__ B2,
    const float* __restrict__ bias, const float* __restrict__ res,
    const float* __restrict__ aux,  float* __restrict__ C,
    __nv_bfloat16* __restrict__ Cb, int N, int K)
{
    if (MODE == EP_HEAD) {      // grid.z selects q/k/v weight + output slab
        if (blockIdx.z == 1)      { B = B1; C += (size_t)T_ * D_; }
        else if (blockIdx.z == 2) { B = B2; C += (size_t)2 * T_ * D_; }
    }
    __shared__ __nv_bfloat16 As[2][BM][HP];
    __shared__ __nv_bfloat16 Bs[2][BN][HP];
    int tid = threadIdx.x;
    int warp = tid >> 5, lane = tid & 31;
    int g = lane >> 2, tg = lane & 3;
    int wm = warp >> 2, wn = warp & 3;
    int m0 = blockIdx.y * BM, n0 = blockIdx.x * BN;

    float acc[4][4][4] = {};
    int nk = K / HKB;

    // 16B cp.async: 128 rows x 64B per tile = 512 chunks, 2 per thread
    #define CPA(buf, kt) do {                                                   \
        int k0_ = (kt) * HKB;                                                   \
        _Pragma("unroll")                                                       \
        for (int e = 0; e < 2; e++) {                                           \
            int idx = tid + e * 256;                                            \
            int r_ = idx >> 2, c_ = (idx & 3) * 8;                              \
            const __nv_bfloat16* src_ = A + (size_t)(m0 + r_) * K + k0_ + c_;   \
            unsigned dst_ = (unsigned)__cvta_generic_to_shared(&As[buf][r_][c_]); \
            asm volatile("cp.async.cg.shared.global [%0], [%1], 16;\n"          \
                         :: "r"(dst_), "l"(src_));                              \
        }                                                                       \
    } while (0)
    #define CPB(buf, kt) do {                                                   \
        int k0_ = (kt) * HKB;                                                   \
        _Pragma("unroll")                                                       \
        for (int e = 0; e < 2; e++) {                                           \
            int idx = tid + e * 256;                                            \
            int r_ = idx >> 2, c_ = (idx & 3) * 8;                              \
            const __nv_bfloat16* src_ = B + (size_t)(n0 + r_) * K + k0_ + c_;   \
            unsigned dst_ = (unsigned)__cvta_generic_to_shared(&Bs[buf][r_][c_]); \
            asm volatile("cp.async.cg.shared.global [%0], [%1], 16;\n"          \
                         :: "r"(dst_), "l"(src_));                              \
        }                                                                       \
    } while (0)

    CPA(0, 0); CPB(0, 0);
    asm volatile("cp.async.commit_group;\n");

    for (int t = 0; t < nk; t++) {
        int buf = t & 1;
        if (t + 1 < nk) {
            CPA(buf ^ 1, t + 1); CPB(buf ^ 1, t + 1);
            asm volatile("cp.async.commit_group;\n");
            asm volatile("cp.async.wait_group 1;\n");
        } else {
            asm volatile("cp.async.wait_group 0;\n");
        }
        __syncthreads();

        #pragma unroll
        for (int ks = 0; ks < 2; ks++) {
            int kb = ks * 16;
            unsigned af[4][4], bfr[4][2];
            #pragma unroll
            for (int i = 0; i < 4; i++) {
                int mr = wm * 64 + i * 16 + g;
                af[i][0] = *(const unsigned*)&As[buf][mr    ][kb + 2 * tg    ];
                af[i][1] = *(const unsigned*)&As[buf][mr + 8][kb + 2 * tg    ];
                af[i][2] = *(const unsigned*)&As[buf][mr    ][kb + 2 * tg + 8];
                af[i][3] = *(const unsigned*)&As[buf][mr + 8][kb + 2 * tg + 8];
            }
            #pragma unroll
            for (int j = 0; j < 4; j++) {
                int nc = wn * 32 + j * 8 + g;
                bfr[j][0] = *(const unsigned*)&Bs[buf][nc][kb + 2 * tg    ];
                bfr[j][1] = *(const unsigned*)&Bs[buf][nc][kb + 2 * tg + 8];
            }
            #pragma unroll
            for (int i = 0; i < 4; i++)
                #pragma unroll
                for (int j = 0; j < 4; j++)
                    MMA_BF16(acc[i][j], af[i][0], af[i][1], af[i][2], af[i][3],
                             bfr[j][0], bfr[j][1]);
        }
        __syncthreads();
    }

    // --- epilogue ---
    #pragma unroll
    for (int i = 0; i < 4; i++) {
        int rbase = m0 + wm * 64 + i * 16 + g;
        #pragma unroll
        for (int j = 0; j < 4; j++) {
            int cbase = n0 + wn * 32 + j * 8 + tg * 2;
            #pragma unroll
            for (int hh = 0; hh < 2; hh++) {
                int rr = rbase + hh * 8;
                #pragma unroll
                for (int cc = 0; cc < 2; cc++) {
                    int nn = cbase + cc;
                    float v = acc[i][j][hh * 2 + cc];
                    if (MODE == EP_HEAD) {
                        C[(size_t)((nn >> 6) * T_ + rr) * 64 + (nn & 63)] = v;
                    } else if (MODE == EP_BIASRES) {
                        C[(size_t)rr * N + nn] = v + bias[nn] + res[(size_t)rr * N + nn];
                    } else if (MODE == EP_BIAS) {
                        C[(size_t)rr * N + nn] = v + bias[nn];
                    } else { // EP_SWIGLU: bf16 out = silu(aux) * (acc + bias)
                        float a = aux[(size_t)rr * N + nn];
                        float sig = 1.f / (1.f + __expf(-a));
                        Cb[(size_t)rr * N + nn] = __float2bfloat16((a * sig) * (v + bias[nn]));
                    }
                }
            }
        }
    }
    #undef CPA
    #undef CPB
}

// ---------------- causal flash attention, tf32 MMA ---------------------------
#define FAP 68

__global__ void __launch_bounds__(256) attn_mma_kernel(
    const float* __restrict__ q, const float* __restrict__ k,
    const float* __restrict__ v, __nv_bfloat16* __restrict__ ctx)
{
    extern __shared__ float sm[];
    float* Ks = sm;
    float* Vs = Ks + 64 * FAP;
    float* Ps = Vs + 64 * FAP;

    int tid = threadIdx.x;
    int warp = tid >> 5, lane = tid & 31;
    int g = lane >> 2, tg = lane & 3;
    int qt = gridDim.x - 1 - blockIdx.x;
    int h = blockIdx.y;
    int qm0 = qt * 128;
    const float* qh = q + (size_t)h * (T_ * HD_);
    const float* kh = k + (size_t)h * (T_ * HD_);
    const float* vh = v + (size_t)h * (T_ * HD_);

    int r0 = qm0 + warp * 16 + g;
    int r1 = r0 + 8;

    unsigned qf[8][4];
    #pragma unroll
    for (int kc = 0; kc < 8; kc++) {
        qf[kc][0] = cvt_tf32(qh[(size_t)r0 * 64 + kc * 8 + tg    ] * 0.125f);
        qf[kc][1] = cvt_tf32(qh[(size_t)r1 * 64 + kc * 8 + tg    ] * 0.125f);
        qf[kc][2] = cvt_tf32(qh[(size_t)r0 * 64 + kc * 8 + tg + 4] * 0.125f);
        qf[kc][3] = cvt_tf32(qh[(size_t)r1 * 64 + kc * 8 + tg + 4] * 0.125f);
    }

    float oacc[8][4] = {};
    float m0 = -1e30f, m1 = -1e30f, l0 = 0.f, l1 = 0.f;
    int nkt = 2 * qt + 2;

    for (int kt = 0; kt < nkt; kt++) {
        int km0 = kt * 64;
        __syncthreads();
        #pragma unroll
        for (int e = 0; e < 4; e++) {
            int idx = tid + e * 256;
            int r = idx >> 4, d4 = (idx & 15) * 4;
            *(float4*)&Ks[r * FAP + d4] = *(const float4*)&kh[(size_t)(km0 + r) * 64 + d4];
            *(float4*)&Vs[r * FAP + d4] = *(const float4*)&vh[(size_t)(km0 + r) * 64 + d4];
        }
        __syncthreads();

        float sacc[8][4] = {};
        #pragma unroll
        for (int kc = 0; kc < 8; kc++) {
            #pragma unroll
            for (int j = 0; j < 8; j++) {
                unsigned b0 = cvt_tf32(Ks[(j * 8 + g) * FAP + kc * 8 + tg    ]);
                unsigned b1 = cvt_tf32(Ks[(j * 8 + g) * FAP + kc * 8 + tg + 4]);
                MMA_TF32(sacc[j], qf[kc][0], qf[kc][1], qf[kc][2], qf[kc][3], b0, b1);
            }
        }

        if (km0 + 63 > qm0 + warp * 16) {
            #pragma unroll
            for (int j = 0; j < 8; j++) {
                int c0 = km0 + j * 8 + tg * 2, c1 = c0 + 1;
                if (c0 > r0) sacc[j][0] = -1e30f;
                if (c1 > r0) sacc[j][1] = -1e30f;
                if (c0 > r1) sacc[j][2] = -1e30f;
                if (c1 > r1) sacc[j][3] = -1e30f;
            }
        }

        float t0 = -1e30f, t1 = -1e30f;
        #pragma unroll
        for (int j = 0; j < 8; j++) {
            t0 = fmaxf(t0, fmaxf(sacc[j][0], sacc[j][1]));
            t1 = fmaxf(t1, fmaxf(sacc[j][2], sacc[j][3]));
        }
        t0 = fmaxf(t0, __shfl_xor_sync(0xffffffffu, t0, 1));
        t0 = fmaxf(t0, __shfl_xor_sync(0xffffffffu, t0, 2));
        t1 = fmaxf(t1, __shfl_xor_sync(0xffffffffu, t1, 1));
        t1 = fmaxf(t1, __shfl_xor_sync(0xffffffffu, t1, 2));
        float nm0 = fmaxf(m0, t0), nm1 = fmaxf(m1, t1);
        float rs0 = __expf(m0 - nm0), rs1 = __expf(m1 - nm1);
        m0 = nm0; m1 = nm1;

        int pr0 = (warp * 16 + g) * FAP, pr1 = pr0 + 8 * FAP;
        float sum0 = 0.f, sum1 = 0.f;
        #pragma unroll
        for (int j = 0; j < 8; j++) {
            float p00 = __expf(sacc[j][0] - m0);
            float p01 = __expf(sacc[j][1] - m0);
            float p10 = __expf(sacc[j][2] - m1);
            float p11 = __expf(sacc[j][3] - m1);
            sum0 += p00 + p01; sum1 += p10 + p11;
            int c = j * 8 + tg * 2;
            Ps[pr0 + c] = p00; Ps[pr0 + c + 1] = p01;
            Ps[pr1 + c] = p10; Ps[pr1 + c + 1] = p11;
        }
        l0 = l0 * rs0 + sum0;
        l1 = l1 * rs1 + sum1;
        #pragma unroll
        for (int j = 0; j < 8; j++) {
            oacc[j][0] *= rs0; oacc[j][1] *= rs0;
            oacc[j][2] *= rs1; oacc[j][3] *= rs1;
        }
        __syncwarp();

        #pragma unroll
        for (int kc = 0; kc < 8; kc++) {
            unsigned a0 = cvt_tf32(Ps[pr0 + kc * 8 + tg    ]);
            unsigned a1 = cvt_tf32(Ps[pr1 + kc * 8 + tg    ]);
            unsigned a2 = cvt_tf32(Ps[pr0 + kc * 8 + tg + 4]);
            unsigned a3 = cvt_tf32(Ps[pr1 + kc * 8 + tg + 4]);
            #pragma unroll
            for (int j = 0; j < 8; j++) {
                unsigned b0 = cvt_tf32(Vs[(kc * 8 + tg    ) * FAP + j * 8 + g]);
                unsigned b1 = cvt_tf32(Vs[(kc * 8 + tg + 4) * FAP + j * 8 + g]);
                MMA_TF32(oacc[j], a0, a1, a2, a3, b0, b1);
            }
        }
        __syncwarp();
    }

    l0 += __shfl_xor_sync(0xffffffffu, l0, 1);
    l0 += __shfl_xor_sync(0xffffffffu, l0, 2);
    l1 += __shfl_xor_sync(0xffffffffu, l1, 1);
    l1 += __shfl_xor_sync(0xffffffffu, l1, 2);
    float inv0 = 1.f / l0, inv1 = 1.f / l1;
    #pragma unroll
    for (int j = 0; j < 8; j++) {
        int col = h * 64 + j * 8 + tg * 2;
        ctx[(size_t)r0 * D_ + col    ] = __float2bfloat16(oacc[j][0] * inv0);
        ctx[(size_t)r0 * D_ + col + 1] = __float2bfloat16(oacc[j][1] * inv0);
        ctx[(size_t)r1 * D_ + col    ] = __float2bfloat16(oacc[j][2] * inv1);
        ctx[(size_t)r1 * D_ + col + 1] = __float2bfloat16(oacc[j][3] * inv1);
    }
}

// ---------------- launch -----------------------------------------------------
extern "C" void kernel_launch(void* const* d_in, const int* in_sizes, int n_in,
                              void* d_out, int out_size) {
    const float* x  = (const float*)d_in[0];
    const float* Wq = (const float*)d_in[1];
    const float* Wk = (const float*)d_in[2];
    const float* Wv = (const float*)d_in[3];
    const float* Wo = (const float*)d_in[4];
    const float* bo = (const float*)d_in[5];
    const float* w1 = (const float*)d_in[6];
    const float* b1 = (const float*)d_in[7];
    const float* w2 = (const float*)d_in[8];
    const float* b2 = (const float*)d_in[9];
    const float* w3 = (const float*)d_in[10];
    const float* b3 = (const float*)d_in[11];
    const float* g1 = (const float*)d_in[12];
    const float* s1 = (const float*)d_in[13];
    const float* g2 = (const float*)d_in[14];
    const float* s2 = (const float*)d_in[15];
    float* out = (float*)d_out;

    __nv_bfloat16 *hb, *ctxb, *ffb, *Wqb, *Wkb, *Wvb, *Wob, *w1b, *w2b, *w3b;
    float *qkvb, *x2b, *y1b;
    cudaGetSymbolAddress((void**)&hb,   g_hb);
    cudaGetSymbolAddress((void**)&qkvb, g_qkv);
    cudaGetSymbolAddress((void**)&ctxb, g_ctxb);
    cudaGetSymbolAddress((void**)&x2b,  g_x2);
    cudaGetSymbolAddress((void**)&y1b,  g_y1);
    cudaGetSymbolAddress((void**)&ffb,  g_ffb);
    cudaGetSymbolAddress((void**)&Wqb,  g_Wqb);
    cudaGetSymbolAddress((void**)&Wkb,  g_Wkb);
    cudaGetSymbolAddress((void**)&Wvb,  g_Wvb);
    cudaGetSymbolAddress((void**)&Wob,  g_Wob);
    cudaGetSymbolAddress((void**)&w1b,  g_w1b);
    cudaGetSymbolAddress((void**)&w2b,  g_w2b);
    cudaGetSymbolAddress((void**)&w3b,  g_w3b);

    const int attn_smem = (64 * FAP + 64 * FAP + 128 * FAP) * (int)sizeof(float);
    cudaFuncSetAttribute(attn_mma_kernel, cudaFuncAttributeMaxDynamicSharedMemorySize, attn_smem);

    dim3 wblk(32, 8);
    // weight prepass: fp32 [K][N] -> bf16 [N][K]
    wconv_kernel<<<dim3(D_ / 32, D_ / 32), wblk>>>(Wq, Wqb, D_, D_);
    wconv_kernel<<<dim3(D_ / 32, D_ / 32), wblk>>>(Wk, Wkb, D_, D_);
    wconv_kernel<<<dim3(D_ / 32, D_ / 32), wblk>>>(Wv, Wvb, D_, D_);
    wconv_kernel<<<dim3(D_ / 32, D_ / 32), wblk>>>(Wo, Wob, D_, D_);
    wconv_kernel<<<dim3(FF_ / 32, D_ / 32), wblk>>>(w1, w1b, D_, FF_);
    wconv_kernel<<<dim3(FF_ / 32, D_ / 32), wblk>>>(w2, w2b, D_, FF_);
    wconv_kernel<<<dim3(D_ / 32, FF_ / 32), wblk>>>(w3, w3b, FF_, D_);

    dim3 gD(D_ / BN, T_ / BM);        // (6, 32)
    dim3 gQKV(D_ / BN, T_ / BM, 3);   // fused QKV
    dim3 gF(FF_ / BN, T_ / BM);       // (24, 32)

    // 1. LN1 (bf16 out)
    ln_kernel<<<T_, 256>>>(x, g1, s1, hb);
    // 2. fused QKV projections (head-major fp32 out)
    bf16_gemm<EP_HEAD><<<gQKV, 256>>>(hb, Wqb, Wkb, Wvb, nullptr, nullptr, nullptr,
                                      qkvb, nullptr, D_, D_);
    // 3. causal attention (tf32 MMA; bf16 ctx out)
    attn_mma_kernel<<<dim3(T_ / 128, H_), 256, attn_smem>>>(
        qkvb, qkvb + (size_t)T_ * D_, qkvb + (size_t)2 * T_ * D_, ctxb);
    // 4. out projection + bias + residual (fp32 out)
    bf16_gemm<EP_BIASRES><<<gD, 256>>>(ctxb, Wob, nullptr, nullptr, bo, x, nullptr,
                                       x2b, nullptr, D_, D_);
    // 5. LN2 (bf16 out)
    ln_kernel<<<T_, 256>>>(x2b, g2, s2, hb);
    // 6. SwiGLU: y1 = h@w1+b1 (fp32) ; ff = silu(y1) * (h@w2+b2) (bf16)
    bf16_gemm<EP_BIAS>  <<<gF, 256>>>(hb, w1b, nullptr, nullptr, b1, nullptr, nullptr,
                                      y1b, nullptr, FF_, D_);
    bf16_gemm<EP_SWIGLU><<<gF, 256>>>(hb, w2b, nullptr, nullptr, b2, nullptr, y1b,
                                      nullptr, ffb, FF_, D_);
    // 7. down projection + bias + residual -> output (fp32)
    bf16_gemm<EP_BIASRES><<<gD, 256>>>(ffb, w3b, nullptr, nullptr, b3, x2b, nullptr,
                                       out, nullptr, D_, FF_);
}